// round 6
// baseline (speedup 1.0000x reference)
#include <cuda_runtime.h>

#define NB    4
#define NPTS  8192
#define TPB   128
#define TQ    4
#define QB    (TPB*TQ)        // 512 queries per block
#define MT    1024            // targets per chunk
#define NCH   (NPTS/MT)       // 8 chunks
#define NZDIM (2*NB)          // 8 (dir,batch) slices

// Scratch (static device globals; no allocations):
__device__ float    g_pmin[NZDIM*NCH*NPTS];   // [z][chunk][qg] partial mins, 2 MB
__device__ float    g_part[128];
__device__ unsigned g_ticket = 0;             // self-resetting reduction ticket

__device__ __forceinline__ unsigned long long pk2(float lo, float hi) {
    unsigned long long r;
    asm("mov.b64 %0, {%1,%2};" : "=l"(r) : "f"(lo), "f"(hi));
    return r;
}

// Fused pass: blockIdx.z = (batch<<1)|dir; blockIdx.y = target chunk; blockIdx.x = query block.
// dir=0: queries=array1, targets=array2 ; dir=1: queries=array2, targets=array1.
// Each block transforms its target chunk into shared (pair-interleaved, negated, +h bias),
// runs the packed-FFMA2 distance loop, and stores per-chunk partial mins (no atomics).
__global__ __launch_bounds__(TPB) void pass_kernel(const float* __restrict__ q1,
                                                   const float* __restrict__ q2) {
    int dir = blockIdx.z & 1;
    int b   = blockIdx.z >> 1;
    const float* qraw = dir ? q2 : q1;
    const float* traw = dir ? q1 : q2;

    __shared__ ulonglong2 sh[MT];   // 16 KB: 512 pairs * 2 entries

    // On-the-fly target transform: pair p -> {(-x0,-x1),(-y0,-y1)} , {(-z0,-z1),(h0,h1)}
    {
        const float* tsrc = traw + (size_t)(b * NPTS + blockIdx.y * MT) * 3;
        for (int i = threadIdx.x; i < MT / 2; i += TPB) {
            const float* s = tsrc + i * 6;
            float2 v0 = *(const float2*)(s);       // x0 y0
            float2 v1 = *(const float2*)(s + 2);   // z0 x1
            float2 v2 = *(const float2*)(s + 4);   // y1 z1
            float x0 = v0.x, y0 = v0.y, z0 = v1.x;
            float x1 = v1.y, y1 = v2.x, z1 = v2.y;
            float h0 = 0.5f * (x0*x0 + y0*y0 + z0*z0);
            float h1 = 0.5f * (x1*x1 + y1*y1 + z1*z1);
            sh[2*i    ] = make_ulonglong2(pk2(-x0, -x1), pk2(-y0, -y1));
            sh[2*i + 1] = make_ulonglong2(pk2(-z0, -z1), pk2( h0,  h1));
        }
    }

    // Query splats
    unsigned long long X2[TQ], Y2[TQ], Z2[TQ];
    float mnlo[TQ], mnhi[TQ];
#pragma unroll
    for (int k = 0; k < TQ; k++) {
        int qg = b * NPTS + blockIdx.x * QB + threadIdx.x + k * TPB;
        float x = qraw[3*qg], y = qraw[3*qg+1], z = qraw[3*qg+2];
        X2[k] = pk2(x, x); Y2[k] = pk2(y, y); Z2[k] = pk2(z, z);
        mnlo[k] = __int_as_float(0x7f800000);
        mnhi[k] = __int_as_float(0x7f800000);
    }
    __syncthreads();

#pragma unroll 4
    for (int p = 0; p < MT / 2; ++p) {
        ulonglong2 u0 = sh[2*p];       // NX, NY (register pairs straight from LDS.128)
        ulonglong2 u1 = sh[2*p + 1];   // NZ, H
#pragma unroll
        for (int k = 0; k < TQ; k++) {
            float lo, hi;
            // e = h - (xq*xt + yq*yt + zq*zt), two targets per packed op
            asm("{\n\t.reg .b64 t;\n\t"
                "fma.rn.f32x2 t, %2, %3, %4;\n\t"
                "fma.rn.f32x2 t, %5, %6, t;\n\t"
                "fma.rn.f32x2 t, %7, %8, t;\n\t"
                "mov.b64 {%0,%1}, t;\n\t}"
                : "=f"(lo), "=f"(hi)
                : "l"(Z2[k]), "l"(u1.x), "l"(u1.y),
                  "l"(Y2[k]), "l"(u0.y),
                  "l"(X2[k]), "l"(u0.x));
            mnlo[k] = fminf(mnlo[k], lo);
            mnhi[k] = fminf(mnhi[k], hi);
        }
    }

    // Coalesced per-chunk partial-min store (no atomics, no init needed)
    int base = (blockIdx.z * NCH + blockIdx.y) * NPTS + blockIdx.x * QB + threadIdx.x;
#pragma unroll
    for (int k = 0; k < TQ; k++)
        g_pmin[base + k * TPB] = fminf(mnlo[k], mnhi[k]);
}

// Single reduce: fold 8 chunk-mins per query, add a^2 + 2*e, block-sum, ticket-fold.
__global__ void reduce_kernel(const float* __restrict__ q1,
                              const float* __restrict__ q2,
                              float* __restrict__ out) {
    int t = blockIdx.x * 256 + threadIdx.x;     // 0..32767
    float s = 0.f;
#pragma unroll
    for (int i = 0; i < 2; i++) {
        int idx = t + i * 32768;                // 0..65535 = z*8192 + qg
        int z   = idx >> 13;
        int qg  = idx & (NPTS - 1);
        int dir = z & 1, b = z >> 1;
        const float* qraw = dir ? q2 : q1;
        const float* pm = &g_pmin[(z * NCH) * NPTS + qg];
        float m = pm[0];
#pragma unroll
        for (int c = 1; c < NCH; c++) m = fminf(m, pm[c * NPTS]);
        const float* qa = qraw + (size_t)(b * NPTS + qg) * 3;
        float ax = qa[0], ay = qa[1], az = qa[2];
        s += (ax*ax + ay*ay + az*az) + 2.0f * m;
    }

    // block reduction (256 threads)
#pragma unroll
    for (int o = 16; o > 0; o >>= 1) s += __shfl_down_sync(0xFFFFFFFFu, s, o);
    __shared__ float ws[8];
    __shared__ unsigned s_tk;
    if ((threadIdx.x & 31) == 0) ws[threadIdx.x >> 5] = s;
    __syncthreads();
    if (threadIdx.x == 0) {
        float bs = 0.f;
#pragma unroll
        for (int w = 0; w < 8; w++) bs += ws[w];
        g_part[blockIdx.x] = bs;
        __threadfence();
        s_tk = atomicAdd(&g_ticket, 1u);
    }
    __syncthreads();

    // Last block folds all partials (deterministic order) and writes output.
    if (s_tk == 127u && threadIdx.x < 32) {
        __threadfence();
        float v = g_part[threadIdx.x]      + g_part[threadIdx.x + 32]
                + g_part[threadIdx.x + 64] + g_part[threadIdx.x + 96];
#pragma unroll
        for (int o = 16; o > 0; o >>= 1) v += __shfl_down_sync(0xFFFFFFFFu, v, o);
        if (threadIdx.x == 0) {
            out[0] = v * (1.0f / (float)(NB * NPTS));
            g_ticket = 0;   // reset for next graph replay
        }
    }
}

extern "C" void kernel_launch(void* const* d_in, const int* in_sizes, int n_in,
                              void* d_out, int out_size) {
    const float* a1 = (const float*)d_in[0];   // array1 [4,8192,3]
    const float* a2 = (const float*)d_in[1];   // array2 [4,8192,3]
    float* out = (float*)d_out;

    dim3 grid(NPTS / QB, NCH, NZDIM);          // (16, 8, 8) = 1024 blocks, single wave
    pass_kernel<<<grid, TPB>>>(a1, a2);
    reduce_kernel<<<128, 256>>>(a1, a2, out);
}

// round 7
// speedup vs baseline: 1.1769x; 1.1769x over previous
#include <cuda_runtime.h>

#define NB     4
#define NPTS   8192
#define TPB    128
#define TQ     4
#define QB     (TPB*TQ)       // 512 queries per block
#define MC     512            // targets per block chunk (256 pairs, 8 KB shared)
#define NPAIRS (NB*NPTS/2)    // 16384 target pairs per array
#define ASZ    (NB*NPTS)      // 32768 points per array

// Scratch (static device globals; no allocations):
__device__ float4   g_prep[2*ASZ];   // [which][pair-interleaved]; which=0: array1, 1: array2
__device__ unsigned g_enc[2*ASZ];    // [dir][point] encoded min(e); dir=0: array1 queries
__device__ float    g_part[64];
__device__ unsigned g_ticket = 0;    // self-resetting reduction ticket

__device__ __forceinline__ unsigned long long pk2(float lo, float hi) {
    unsigned long long r;
    asm("mov.b64 %0, {%1,%2};" : "=l"(r) : "f"(lo), "f"(hi));
    return r;
}
// Order-preserving float->uint encoding (handles negatives) for atomicMin.
__device__ __forceinline__ unsigned fenc(float f) {
    unsigned b = __float_as_uint(f);
    return b ^ ((b & 0x80000000u) ? 0xFFFFFFFFu : 0x80000000u);
}
__device__ __forceinline__ float fdec(unsigned u) {
    unsigned b = (u & 0x80000000u) ? (u ^ 0x80000000u) : ~u;
    return __uint_as_float(b);
}

// Pack targets pair-interleaved AND init the matching enc range to +inf.
// blockIdx.y selects source array. For pair p (points 2p,2p+1):
//   dst[2p]   = (-x0,-x1,-y0,-y1)
//   dst[2p+1] = (-z0,-z1, h0, h1)   with h = 0.5*(x^2+y^2+z^2)
__global__ void prep_kernel(const float* __restrict__ a1, const float* __restrict__ a2) {
    int which = blockIdx.y;
    const float* src = which ? a2 : a1;
    float4*      dst = g_prep + which * ASZ;
    unsigned*    enc = g_enc  + which * ASZ;   // enc[0]=array1 queries pairs with prep[0]
    int p = blockIdx.x * blockDim.x + threadIdx.x;
    const float* s = src + p * 6;              // batch boundaries are pair-aligned
    float x0 = s[0], y0 = s[1], z0 = s[2];
    float x1 = s[3], y1 = s[4], z1 = s[5];
    float h0 = 0.5f * (x0*x0 + y0*y0 + z0*z0);
    float h1 = 0.5f * (x1*x1 + y1*y1 + z1*z1);
    dst[2*p    ] = make_float4(-x0, -x1, -y0, -y1);
    dst[2*p + 1] = make_float4(-z0, -z1,  h0,  h1);
    enc[2*p    ] = 0xFFFFFFFFu;
    enc[2*p + 1] = 0xFFFFFFFFu;
}

// Fused both directions: blockIdx.z = (batch<<1)|dir, grid (16,16,8)=2048 blocks.
// dir=0: queries=array1, targets=prep(array2); dir=1: queries=array2, targets=prep(array1).
__global__ __launch_bounds__(TPB) void pass_kernel(const float* __restrict__ q1,
                                                   const float* __restrict__ q2) {
    int dir = blockIdx.z & 1;
    int b   = blockIdx.z >> 1;
    const float*  qraw   = dir ? q2 : q1;
    const float4* tp     = g_prep + (dir ? 0 : ASZ);   // targets = the OTHER array
    unsigned*     encOut = g_enc  + dir * ASZ;

    int q0 = b * NPTS + blockIdx.x * QB;

    __shared__ float4 sh[MC];   // 8 KB: 256 target-pairs * 2 float4

    const float4* gsrc = tp + 2 * (b * (NPTS/2) + blockIdx.y * (MC/2));
    for (int i = threadIdx.x; i < MC; i += TPB) sh[i] = gsrc[i];

    unsigned long long X2[TQ], Y2[TQ], Z2[TQ];
    float mnlo[TQ], mnhi[TQ];
#pragma unroll
    for (int k = 0; k < TQ; k++) {
        int qg = q0 + threadIdx.x + k * TPB;
        float x = qraw[3*qg], y = qraw[3*qg+1], z = qraw[3*qg+2];
        X2[k] = pk2(x, x); Y2[k] = pk2(y, y); Z2[k] = pk2(z, z);
        mnlo[k] = __int_as_float(0x7f800000);
        mnhi[k] = __int_as_float(0x7f800000);
    }
    __syncthreads();

#pragma unroll 2
    for (int p = 0; p < MC / 2; ++p) {
        float4 A  = sh[2*p];
        float4 Bv = sh[2*p + 1];
        unsigned long long NX = pk2(A.x,  A.y);
        unsigned long long NY = pk2(A.z,  A.w);
        unsigned long long NZ = pk2(Bv.x, Bv.y);
        unsigned long long H  = pk2(Bv.z, Bv.w);
        unsigned long long acc[TQ];
        // Stage-interleaved FFMA2 chains: all k's stage-1, then stage-2, then stage-3.
        // Program order has no back-to-back RAW deps -> zero issue bubbles.
#pragma unroll
        for (int k = 0; k < TQ; k++)
            asm("fma.rn.f32x2 %0, %1, %2, %3;" : "=l"(acc[k]) : "l"(Z2[k]), "l"(NZ), "l"(H));
#pragma unroll
        for (int k = 0; k < TQ; k++)
            asm("fma.rn.f32x2 %0, %1, %2, %0;" : "+l"(acc[k]) : "l"(Y2[k]), "l"(NY));
#pragma unroll
        for (int k = 0; k < TQ; k++)
            asm("fma.rn.f32x2 %0, %1, %2, %0;" : "+l"(acc[k]) : "l"(X2[k]), "l"(NX));
#pragma unroll
        for (int k = 0; k < TQ; k++) {
            float lo, hi;
            asm("mov.b64 {%0,%1}, %2;" : "=f"(lo), "=f"(hi) : "l"(acc[k]));
            mnlo[k] = fminf(mnlo[k], lo);
            mnhi[k] = fminf(mnhi[k], hi);
        }
    }

#pragma unroll
    for (int k = 0; k < TQ; k++)
        atomicMin(&encOut[q0 + threadIdx.x + k * TPB],
                  fenc(fminf(mnlo[k], mnhi[k])));
}

// Single fused reduce: dist_point = a^2 + 2e = 2*(h + e); h lives in g_prep[2p+1].z/.w.
// 64 blocks x 256 threads, 2 point-pairs per thread; ticket-fold, deterministic order.
__global__ void reduce_kernel(float* __restrict__ out) {
    int t = threadIdx.x;
    float s = 0.f;
#pragma unroll
    for (int i = 0; i < 2; i++) {
        int pp    = blockIdx.x * 512 + t + i * 256;   // global pair id, 0..32767
        int which = pp >> 14;                          // 16384 pairs per array
        int p     = pp & 16383;
        float4 hv = g_prep[which * ASZ + 2*p + 1];
        const unsigned* enc = g_enc + which * ASZ;     // enc[which] pairs with prep[which]
        s += (hv.z + fdec(enc[2*p])) + (hv.w + fdec(enc[2*p + 1]));
    }
#pragma unroll
    for (int o = 16; o > 0; o >>= 1) s += __shfl_down_sync(0xFFFFFFFFu, s, o);
    __shared__ float ws[8];
    __shared__ unsigned s_tk;
    if ((t & 31) == 0) ws[t >> 5] = s;
    __syncthreads();
    if (t == 0) {
        float bs = ((ws[0] + ws[1]) + (ws[2] + ws[3]))
                 + ((ws[4] + ws[5]) + (ws[6] + ws[7]));
        g_part[blockIdx.x] = bs;
        __threadfence();
        s_tk = atomicAdd(&g_ticket, 1u);
    }
    __syncthreads();

    if (s_tk == 63u && t < 32) {                      // last block folds partials
        __threadfence();
        float v = g_part[t] + g_part[t + 32];
#pragma unroll
        for (int o = 16; o > 0; o >>= 1) v += __shfl_down_sync(0xFFFFFFFFu, v, o);
        if (t == 0) {
            out[0] = v * (2.0f / (float)(NB * NPTS)); // h is a^2/2 -> factor 2
            g_ticket = 0;                             // reset for next graph replay
        }
    }
}

extern "C" void kernel_launch(void* const* d_in, const int* in_sizes, int n_in,
                              void* d_out, int out_size) {
    const float* a1 = (const float*)d_in[0];   // array1 [4,8192,3]
    const float* a2 = (const float*)d_in[1];   // array2 [4,8192,3]
    float* out = (float*)d_out;

    dim3 pgrid(NPAIRS / 256, 2);
    prep_kernel<<<pgrid, 256>>>(a1, a2);

    dim3 grid(NPTS / QB, NPTS / MC, 2 * NB);   // (16,16,8) = 2048 blocks
    pass_kernel<<<grid, TPB>>>(a1, a2);

    reduce_kernel<<<64, 256>>>(out);
}